// round 3
// baseline (speedup 1.0000x reference)
#include <cuda_runtime.h>

#define TT   1000
#define HH   4096
#define PP   16
#define NCTA 32
#define TPB  128   // 1 neuron/thread: 32*128 = 4096

// Cross-CTA mailboxes. Zero-initialized at module load. Across graph replays
// flags stay set; that is safe because every replay writes bit-identical
// values (fully deterministic reduction order), so a stale read returns the
// same float. 4B stores are word-atomic, so torn reads are impossible.
__device__ float    gA[TT * NCTA * PP];      // spike-term partials (critical)
__device__ float    gB[TT * NCTA * PP];      // decay-term partials (published early)
__device__ float    gY[TT * NCTA * 4 * 2];   // per-warp y partials
__device__ unsigned fA[TT * NCTA];
__device__ unsigned fB[TT * NCTA];

__device__ __forceinline__ unsigned ld_acq(const unsigned* p) {
    unsigned v;
    asm volatile("ld.acquire.gpu.global.u32 %0, [%1];" : "=r"(v) : "l"(p) : "memory");
    return v;
}
__device__ __forceinline__ void st_rel(unsigned* p, unsigned v) {
    asm volatile("st.release.gpu.global.u32 [%0], %1;" :: "l"(p), "r"(v) : "memory");
}

// Reduce 16 values across a warp in 16 shuffles (5 dependent levels).
// Even lanes write the warp sum for p = lane>>1 into dst[p].
__device__ __forceinline__ void fold16(const float v[PP], float* dst, int lane) {
    const bool b16 = (lane & 16) != 0;
    float a8[8];
#pragma unroll
    for (int i = 0; i < 8; i++) {
        float send = b16 ? v[i] : v[i + 8];
        float recv = __shfl_xor_sync(0xffffffffu, send, 16);
        a8[i] = (b16 ? v[i + 8] : v[i]) + recv;
    }
    const bool b8 = (lane & 8) != 0;
    float a4[4];
#pragma unroll
    for (int i = 0; i < 4; i++) {
        float send = b8 ? a8[i] : a8[i + 4];
        float recv = __shfl_xor_sync(0xffffffffu, send, 8);
        a4[i] = (b8 ? a8[i + 4] : a8[i]) + recv;
    }
    const bool b4 = (lane & 4) != 0;
    float a2[2];
#pragma unroll
    for (int i = 0; i < 2; i++) {
        float send = b4 ? a2[0] * 0.f + (b4 ? a4[i] : a4[i + 2]) : a4[i + 2]; // placeholder avoided below
        (void)send;
        float s2 = b4 ? a4[i] : a4[i + 2];
        float recv = __shfl_xor_sync(0xffffffffu, s2, 4);
        a2[i] = (b4 ? a4[i + 2] : a4[i]) + recv;
    }
    const bool b2 = (lane & 2) != 0;
    float s1 = b2 ? a2[0] : a2[1];
    float recv = __shfl_xor_sync(0xffffffffu, s1, 2);
    float keep = (b2 ? a2[1] : a2[0]) + recv;
    keep += __shfl_xor_sync(0xffffffffu, keep, 1);
    if ((lane & 1) == 0) dst[lane >> 1] = keep;
}

__global__ void __launch_bounds__(TPB, 1) snn_scan(
    const float* __restrict__ x,      // [T,6]
    const float* __restrict__ noise,  // [T,H]
    const float* __restrict__ Win,    // [H,6]
    const float* __restrict__ Wout,   // [2,H]
    const float* __restrict__ pin,    // [H,16]
    const float* __restrict__ pout,   // [H,16]
    const float* __restrict__ l,      // [16]
    const float* __restrict__ stau)   // [H]
{
    const int cta  = blockIdx.x;
    const int tid  = threadIdx.x;
    const int lane = tid & 31;
    const int warp = tid >> 5;
    const int h    = cta * TPB + tid;

    // ---- per-neuron constants in registers ----
    const float stv = stau[h];
    const float tau = 1.0f / (1.0f + expf(-stv)) * 0.03f + 0.02f;
    const float dd  = expf(-0.005f / tau);          // decay_d
    const float sg  = 0.005f / (tau * 0.002f);      // s_gain
    const float dr  = 0.08208499862389880f;         // exp(-2.5)
    const float cA  = 0.005f * sg;                  // DT*sg
    const float invcA = tau * 80.0f;                // 1/cA  (cA = 0.0125/tau)

    float lp[PP], kA[PP];
#pragma unroll
    for (int p = 0; p < PP; p++) {
        lp[p] = l[p] * pin[h * PP + p];
        kA[p] = pout[h * PP + p] * cA;              // po * DT * sg
    }
    float wv[6];
#pragma unroll
    for (int k = 0; k < 6; k++) wv[k] = Win[h * 6 + k];
    const float w0 = Wout[h];
    const float w1 = Wout[HH + h];

    float mem = 0.f, r = 0.f, s = 0.f;
    float qB = 0.f;                                  // warp0 lanes<16: Σ B partials

    __shared__ float q_sm[PP];
    __shared__ float partA[4][PP];
    __shared__ float partB[4][PP];

    if (tid < PP) q_sm[tid] = 0.f;                   // q_0 = 0
    // prefetch t=0 streams
    float nz = noise[h];
    float xv[6];
#pragma unroll
    for (int k = 0; k < 6; k++) xv[k] = x[k];
    __syncthreads();

    for (int t = 0; t < TT; t++) {
        // ================= S: publish B_t (no dependency on incoming q) ====
        const float rbar = dd * r + (0.005f * dr) * s;   // rbar_t from t-1 state
        {
            const float rb = rbar * invcA;               // Σ po*rbar = Σ kA*(rbar/cA)
            float vb[PP];
#pragma unroll
            for (int p = 0; p < PP; p++) vb[p] = kA[p] * rb;
            fold16(vb, partB[warp], lane);
        }
        __syncthreads();
        if (tid < PP) {
            float b = ((partB[0][tid] + partB[1][tid]) + (partB[2][tid] + partB[3][tid]));
            gB[(t * NCTA + cta) * PP + tid] = b;
        }
        __syncthreads();
        if (tid == 0) st_rel(&fB[t * NCTA + cta], 1u);

        // ================= W: assemble q_t = A_{t-1} + B_{t-1} =============
        if (t > 0) {
            if (warp == 0) {
                while (ld_acq(&fA[(t - 1) * NCTA + lane]) == 0u) {}
                __syncwarp();
                if (lane < PP) {
                    const float* ga = &gA[(t - 1) * NCTA * PP + lane];
                    float a0 = 0.f, a1 = 0.f, a2 = 0.f, a3 = 0.f;
#pragma unroll
                    for (int c = 0; c < NCTA; c += 4) {
                        a0 += ga[(c + 0) * PP];
                        a1 += ga[(c + 1) * PP];
                        a2 += ga[(c + 2) * PP];
                        a3 += ga[(c + 3) * PP];
                    }
                    q_sm[lane] = ((a0 + a1) + (a2 + a3)) + qB;
                }
            }
            __syncthreads();
        }

        // ================= C: critical compute + publish A_t ===============
        float I0 = nz / 10.0f + wv[0] * xv[0];
        float I1 = wv[1] * xv[1] + wv[2] * xv[2];
        float I2 = wv[3] * xv[3] + wv[4] * xv[4];
        float I3 = wv[5] * xv[5];
#pragma unroll
        for (int p = 0; p < PP; p += 4) {
            I0 += lp[p + 0] * q_sm[p + 0];
            I1 += lp[p + 1] * q_sm[p + 1];
            I2 += lp[p + 2] * q_sm[p + 2];
            I3 += lp[p + 3] * q_sm[p + 3];
        }
        const float I = (I0 + I1) + (I2 + I3);

        const float reset = (mem > 0.5f) ? 0.5f : 0.0f;   // from incoming mem
        mem = 0.9f * mem + I - reset;
        const bool spike = (mem > 0.5f);

        {
            float va[PP];
#pragma unroll
            for (int p = 0; p < PP; p++) va[p] = spike ? kA[p] : 0.0f;
            fold16(va, partA[warp], lane);
        }
        __syncthreads();
        if (tid < PP) {
            float a = ((partA[0][tid] + partA[1][tid]) + (partA[2][tid] + partA[3][tid]));
            gA[(t * NCTA + cta) * PP + tid] = a;
        }
        __syncthreads();
        if (tid == 0) st_rel(&fA[t * NCTA + cta], 1u);

        // ================= D: slack work (hidden under peers' flight) ======
        s = s * dr + (spike ? sg : 0.0f);
        r = dd * r + 0.005f * s;

        // y partials (per warp, no CTA combine)
        float y0 = w0 * r, y1 = w1 * r;
#pragma unroll
        for (int o = 16; o > 0; o >>= 1) {
            y0 += __shfl_xor_sync(0xffffffffu, y0, o);
            y1 += __shfl_xor_sync(0xffffffffu, y1, o);
        }
        if (lane == 0) {
            float* gy = &gY[((t * NCTA + cta) * 4 + warp) * 2];
            gy[0] = y0;
            gy[1] = y1;
        }

        // prefetch next step's streams
        if (t + 1 < TT) {
            nz = noise[(t + 1) * HH + h];
#pragma unroll
            for (int k = 0; k < 6; k++) xv[k] = x[(t + 1) * 6 + k];
        }

        // warp0: pre-gather B_t for next step's q (off critical path)
        if (warp == 0) {
            while (ld_acq(&fB[t * NCTA + lane]) == 0u) {}
            __syncwarp();
            if (lane < PP) {
                const float* gb = &gB[t * NCTA * PP + lane];
                float b0 = 0.f, b1 = 0.f, b2 = 0.f, b3 = 0.f;
#pragma unroll
                for (int c = 0; c < NCTA; c += 4) {
                    b0 += gb[(c + 0) * PP];
                    b1 += gb[(c + 1) * PP];
                    b2 += gb[(c + 2) * PP];
                    b3 += gb[(c + 3) * PP];
                }
                qB = (b0 + b1) + (b2 + b3);
            }
        }
    }
}

// y[t,o] = sum of the 128 per-warp partials (deterministic order)
__global__ void reduce_y(float* __restrict__ out)
{
    int i = blockIdx.x * blockDim.x + threadIdx.x;
    if (i < TT * 2) {
        int t = i >> 1, o = i & 1;
        const float* base = &gY[t * NCTA * 4 * 2 + o];
        float a0 = 0.f, a1 = 0.f, a2 = 0.f, a3 = 0.f;
#pragma unroll
        for (int j = 0; j < NCTA * 4; j += 4) {
            a0 += base[(j + 0) * 2];
            a1 += base[(j + 1) * 2];
            a2 += base[(j + 2) * 2];
            a3 += base[(j + 3) * 2];
        }
        out[i] = (a0 + a1) + (a2 + a3);
    }
}

extern "C" void kernel_launch(void* const* d_in, const int* in_sizes, int n_in,
                              void* d_out, int out_size)
{
    const float* x     = (const float*)d_in[0];
    const float* noise = (const float*)d_in[1];
    const float* Win   = (const float*)d_in[2];
    const float* Wout  = (const float*)d_in[3];
    const float* pin   = (const float*)d_in[4];
    const float* pout  = (const float*)d_in[5];
    const float* l     = (const float*)d_in[6];
    const float* stau  = (const float*)d_in[7];
    float* out = (float*)d_out;

    snn_scan<<<NCTA, TPB>>>(x, noise, Win, Wout, pin, pout, l, stau);
    reduce_y<<<(TT * 2 + 255) / 256, 256>>>(out);
}

// round 4
// speedup vs baseline: 1.6328x; 1.6328x over previous
#include <cuda_runtime.h>

#define TT   1000
#define HH   4096
#define PP   16
#define NCTA 16
#define TPB  256
#define NW   (TPB / 32)   // 8 warps per CTA

// Cross-CTA mailboxes + scratch. Zero-initialized at module load. Across graph
// replays the flags stay set from the previous replay; that is safe because
// every replay writes bit-identical values (fully deterministic reduction
// order), so a stale read returns the identical float. 4B stores are
// word-atomic, so torn reads are impossible.
__device__ float    g_pre[TT * HH];                 // Win@x + noise/10
__device__ __align__(128) float g_msg[TT * NCTA * 32];  // [A_t(16) | B_{t+1}(16)] per CTA
__device__ unsigned g_flag[TT * NCTA];
__device__ float    g_y[TT * NCTA * NW * 2];        // per-warp y partials

__device__ __forceinline__ unsigned ld_acq(const unsigned* p) {
    unsigned v;
    asm volatile("ld.acquire.gpu.global.u32 %0, [%1];" : "=r"(v) : "l"(p) : "memory");
    return v;
}
__device__ __forceinline__ void st_rel(unsigned* p, unsigned v) {
    asm volatile("st.release.gpu.global.u32 [%0], %1;" :: "l"(p), "r"(v) : "memory");
}

// Warp-wide reduction of 32 per-lane values in 31 shuffles (5 dependent
// levels). On return, the value at index j (summed over all 32 lanes) is held
// by lane j.
__device__ __forceinline__ float fold32(float v[32], int lane) {
#pragma unroll
    for (int m = 16; m >= 1; m >>= 1) {
        const bool hi = (lane & m) != 0;
#pragma unroll
        for (int i = 0; i < m; i++) {
            float keep = hi ? v[i + m] : v[i];
            float send = hi ? v[i] : v[i + m];
            float recv = __shfl_xor_sync(0xffffffffu, send, m);
            v[i] = keep + recv;
        }
    }
    return v[0];
}

// pre[t][h] = Win[h,:]@x[t,:] + noise[t,h]/10
__global__ void pre_kernel(const float* __restrict__ noise,
                           const float* __restrict__ x,
                           const float* __restrict__ Win)
{
    int i = blockIdx.x * blockDim.x + threadIdx.x;
    if (i < TT * HH) {
        int t = i / HH, h = i - t * HH;
        float acc = noise[i] * 0.1f;
        const float* wr = &Win[h * 6];
        const float* xr = &x[t * 6];
#pragma unroll
        for (int k = 0; k < 6; k++) acc += wr[k] * xr[k];
        g_pre[i] = acc;
    }
}

__global__ void __launch_bounds__(TPB, 1) snn_scan(
    const float* __restrict__ Wout,   // [2,H]
    const float* __restrict__ pin,    // [H,16]
    const float* __restrict__ pout,   // [H,16]
    const float* __restrict__ l,      // [16]
    const float* __restrict__ stau)   // [H]
{
    const int cta  = blockIdx.x;
    const int tid  = threadIdx.x;
    const int lane = tid & 31;
    const int warp = tid >> 5;
    const int h    = cta * TPB + tid;

    // ---- per-neuron constants in registers ----
    const float stv    = stau[h];
    const float tau    = 1.0f / (1.0f + expf(-stv)) * 0.03f + 0.02f;
    const float dd     = expf(-0.005f / tau);       // decay_d
    const float sg     = 0.005f / (tau * 0.002f);   // s_gain
    const float dr     = 0.08208499862389880f;      // exp(-DT/TAU_R) = exp(-2.5)
    const float c005dr = 0.005f * dr;               // DT*decay_r
    const float invcA  = tau * 80.0f;               // 1/(DT*sg)

    float lp[PP], kA[PP];
#pragma unroll
    for (int p = 0; p < PP; p++) {
        lp[p] = l[p] * pin[h * PP + p];             // (l*pin)[h,p]
        kA[p] = pout[h * PP + p] * (0.0125f / tau); // po * DT * sg
    }
    const float w0 = Wout[h];
    const float w1 = Wout[HH + h];

    float mem = 0.f, r = 0.f, s = 0.f;
    float bprev = 0.f;   // lanes 0..15: Sum_c B_t[p]; B_0 = 0

    __shared__ float part[2][NW][32];

    float nz = g_pre[h];   // t = 0

    for (int t = 0; t < TT; t++) {
        // ================= consume: q_t = A_{t-1} + B_{t-1} ================
        float q = 0.f;
        if (t > 0) {
            if (lane < NCTA)
                while (ld_acq(&g_flag[(t - 1) * NCTA + lane]) == 0u) {}
            __syncwarp();
            // each producer block is one 128B line; warp reads it coalesced
            const float* m = &g_msg[(t - 1) * NCTA * 32 + lane];
            float s0 = 0.f, s1 = 0.f, s2 = 0.f, s3 = 0.f;
#pragma unroll
            for (int c = 0; c < NCTA; c += 4) {
                s0 += m[(c + 0) * 32];
                s1 += m[(c + 1) * 32];
                s2 += m[(c + 2) * 32];
                s3 += m[(c + 3) * 32];
            }
            float sum  = (s0 + s1) + (s2 + s3);          // lanes0-15: ΣA, 16-31: ΣB_next
            float bnew = __shfl_down_sync(0xffffffffu, sum, 16);
            q = sum + bprev;                             // valid in lanes 0..15
            bprev = bnew;                                // B_t for next step
        }

        // ================= I and membrane update ==========================
        float i0 = nz, i1 = 0.f, i2 = 0.f, i3 = 0.f;
#pragma unroll
        for (int p = 0; p < PP; p += 4) {
            i0 += lp[p + 0] * __shfl_sync(0xffffffffu, q, p + 0);
            i1 += lp[p + 1] * __shfl_sync(0xffffffffu, q, p + 1);
            i2 += lp[p + 2] * __shfl_sync(0xffffffffu, q, p + 2);
            i3 += lp[p + 3] * __shfl_sync(0xffffffffu, q, p + 3);
        }
        const float I = (i0 + i1) + (i2 + i3);

        // prefetch next step's input (lands during next detect window)
        if (t + 1 < TT) nz = g_pre[(t + 1) * HH + h];

        const float reset = (mem > 0.5f) ? 0.5f : 0.0f;   // from incoming mem
        mem = 0.9f * mem + I - reset;
        const bool spike = (mem > 0.5f);

        // state update + next-step decay term
        s = s * dr + (spike ? sg : 0.0f);
        r = dd * r + 0.005f * s;
        const float rbn = (dd * r + c005dr * s) * invcA;  // rbar_{t+1}/cA

        // ================= fold + publish [A_t | B_{t+1}] ==================
        float v[32];
#pragma unroll
        for (int p = 0; p < PP; p++) {
            v[p]      = spike ? kA[p] : 0.0f;   // A_t contribution
            v[16 + p] = kA[p] * rbn;            // B_{t+1} contribution
        }
        part[t & 1][warp][lane] = fold32(v, lane);
        __syncthreads();

        if (warp == 0) {
            const float* pb = &part[t & 1][0][lane];
            float a0 = 0.f, a1 = 0.f;
#pragma unroll
            for (int w = 0; w < NW; w += 2) {
                a0 += pb[(w + 0) * 32];
                a1 += pb[(w + 1) * 32];
            }
            g_msg[(t * NCTA + cta) * 32 + lane] = a0 + a1;
            __syncwarp();
            if (lane == 0) st_rel(&g_flag[t * NCTA + cta], 1u);
        }

        // ================= y partials (off critical path) ==================
        float y0 = w0 * r, y1 = w1 * r;
#pragma unroll
        for (int o = 16; o > 0; o >>= 1) {
            y0 += __shfl_xor_sync(0xffffffffu, y0, o);
            y1 += __shfl_xor_sync(0xffffffffu, y1, o);
        }
        if (lane == 0) {
            float* gy = &g_y[((t * NCTA + cta) * NW + warp) * 2];
            gy[0] = y0;
            gy[1] = y1;
        }
    }
}

// One warp per timestep sums the 128 per-warp partials (deterministic order).
__global__ void reduce_y(float* __restrict__ out)
{
    int t    = blockIdx.x * (blockDim.x / 32) + (threadIdx.x >> 5);
    int lane = threadIdx.x & 31;
    if (t < TT) {
        const float* base = &g_y[t * NCTA * NW * 2];
        float y0 = 0.f, y1 = 0.f;
#pragma unroll
        for (int j = 0; j < 4; j++) {
            int k = lane + j * 32;            // 0..127
            y0 += base[k * 2 + 0];
            y1 += base[k * 2 + 1];
        }
#pragma unroll
        for (int o = 16; o > 0; o >>= 1) {
            y0 += __shfl_xor_sync(0xffffffffu, y0, o);
            y1 += __shfl_xor_sync(0xffffffffu, y1, o);
        }
        if (lane == 0) {
            out[t * 2 + 0] = y0;
            out[t * 2 + 1] = y1;
        }
    }
}

extern "C" void kernel_launch(void* const* d_in, const int* in_sizes, int n_in,
                              void* d_out, int out_size)
{
    const float* x     = (const float*)d_in[0];
    const float* noise = (const float*)d_in[1];
    const float* Win   = (const float*)d_in[2];
    const float* Wout  = (const float*)d_in[3];
    const float* pin   = (const float*)d_in[4];
    const float* pout  = (const float*)d_in[5];
    const float* l     = (const float*)d_in[6];
    const float* stau  = (const float*)d_in[7];
    float* out = (float*)d_out;

    pre_kernel<<<(TT * HH + 255) / 256, 256>>>(noise, x, Win);
    snn_scan<<<NCTA, TPB>>>(Wout, pin, pout, l, stau);
    reduce_y<<<(TT + 7) / 8, 256>>>(out);
}

// round 5
// speedup vs baseline: 1.6556x; 1.0139x over previous
#include <cuda_runtime.h>

#define TT   1000
#define HH   4096
#define PP   16
#define NCTA 8          // one cluster of 8 CTAs (portable max)
#define TPB  512
#define NW   (TPB / 32) // 16 warps per CTA

// Scratch (device globals; no allocation). Rewritten identically every replay.
__device__ float g_pre[TT * HH];             // Win@x + noise/10
__device__ float g_y[TT * NCTA * NW * 2];    // per-warp y partials

// ---- PTX helpers ----------------------------------------------------------
__device__ __forceinline__ unsigned smem_u32(const void* p) {
    return (unsigned)__cvta_generic_to_shared(p);
}
__device__ __forceinline__ unsigned mapa_sh(unsigned local, unsigned rank) {
    unsigned r;
    asm volatile("mapa.shared::cluster.u32 %0, %1, %2;" : "=r"(r) : "r"(local), "r"(rank));
    return r;
}
__device__ __forceinline__ void st_cluster_f32(unsigned addr, float v) {
    asm volatile("st.shared::cluster.f32 [%0], %1;" :: "r"(addr), "f"(v) : "memory");
}
__device__ __forceinline__ void mbar_init(unsigned addr, unsigned cnt) {
    asm volatile("mbarrier.init.shared.b64 [%0], %1;" :: "r"(addr), "r"(cnt) : "memory");
}
__device__ __forceinline__ void mbar_arrive_cluster(unsigned addr) {
    asm volatile("mbarrier.arrive.release.cluster.shared::cluster.b64 _, [%0];"
                 :: "r"(addr) : "memory");
}
__device__ __forceinline__ void mbar_wait_parity(unsigned addr, unsigned parity) {
    unsigned done;
    asm volatile(
        "{\n\t.reg .pred p;\n\t"
        "mbarrier.try_wait.parity.acquire.cluster.shared::cta.b64 p, [%1], %2;\n\t"
        "selp.b32 %0, 1, 0, p;\n\t}"
        : "=r"(done) : "r"(addr), "r"(parity) : "memory");
    if (!done) {
        asm volatile(
            "{\n\t.reg .pred P1;\n\t"
            "WL_%=:\n\t"
            "mbarrier.try_wait.parity.acquire.cluster.shared::cta.b64 P1, [%0], %1, 0x989680;\n\t"
            "@P1 bra.uni WD_%=;\n\t"
            "bra.uni WL_%=;\n\t"
            "WD_%=:\n\t}"
            :: "r"(addr), "r"(parity) : "memory");
    }
}
__device__ __forceinline__ void cluster_sync() {
    asm volatile("barrier.cluster.arrive.aligned;" ::: "memory");
    asm volatile("barrier.cluster.wait.aligned;" ::: "memory");
}
__device__ __forceinline__ unsigned ctarank() {
    unsigned r; asm("mov.u32 %0, %%cluster_ctarank;" : "=r"(r)); return r;
}

// Warp-wide reduction of 32 per-lane values in 31 shuffles (5 dependent
// levels). On return, value j (summed over all lanes) is held by lane j.
__device__ __forceinline__ float fold32(float v[32], int lane) {
#pragma unroll
    for (int m = 16; m >= 1; m >>= 1) {
        const bool hi = (lane & m) != 0;
#pragma unroll
        for (int i = 0; i < m; i++) {
            float keep = hi ? v[i + m] : v[i];
            float send = hi ? v[i] : v[i + m];
            float recv = __shfl_xor_sync(0xffffffffu, send, m);
            v[i] = keep + recv;
        }
    }
    return v[0];
}

// pre[t][h] = Win[h,:]@x[t,:] + noise[t,h]/10
__global__ void pre_kernel(const float* __restrict__ noise,
                           const float* __restrict__ x,
                           const float* __restrict__ Win)
{
    int i = blockIdx.x * blockDim.x + threadIdx.x;
    if (i < TT * HH) {
        int t = i / HH, h = i - t * HH;
        float acc = noise[i] * 0.1f;
        const float* wr = &Win[h * 6];
        const float* xr = &x[t * 6];
#pragma unroll
        for (int k = 0; k < 6; k++) acc += wr[k] * xr[k];
        g_pre[i] = acc;
    }
}

__global__ void __launch_bounds__(TPB, 1) __cluster_dims__(NCTA, 1, 1)
snn_scan(const float* __restrict__ Wout,   // [2,H]
         const float* __restrict__ pin,    // [H,16]
         const float* __restrict__ pout,   // [H,16]
         const float* __restrict__ l,      // [16]
         const float* __restrict__ stau)   // [H]
{
    const int tid  = threadIdx.x;
    const int lane = tid & 31;
    const int warp = tid >> 5;
    const unsigned rank = ctarank();
    const int h    = (int)rank * TPB + tid;

    // msg[slot][producer_cta][32]: [A_t(0..15) | B_{t+1}(16..31)]
    __shared__ __align__(128) float msg[2][NCTA][32];
    __shared__ __align__(128) float part[2][NW][32];
    __shared__ __align__(8)   unsigned long long mbar;

    if (tid == 0) mbar_init(smem_u32(&mbar), NCTA);  // 1 arrive per CTA per phase
    __syncthreads();
    cluster_sync();   // all barriers initialized before any remote arrive

    // ---- per-neuron constants in registers ----
    const float stv    = stau[h];
    const float tau    = 1.0f / (1.0f + expf(-stv)) * 0.03f + 0.02f;
    const float dd     = expf(-0.005f / tau);       // decay_d
    const float sg     = 0.005f / (tau * 0.002f);   // s_gain
    const float dr     = 0.08208499862389880f;      // exp(-DT/TAU_R)
    const float c005dr = 0.005f * dr;               // DT*decay_r
    const float invcA  = tau * 80.0f;               // 1/(DT*sg)

    float lp[PP], kA[PP];
#pragma unroll
    for (int p = 0; p < PP; p++) {
        lp[p] = l[p] * pin[h * PP + p];             // (l*pin)[h,p]
        kA[p] = pout[h * PP + p] * (0.0125f / tau); // po * DT * sg
    }
    const float w0 = Wout[h];
    const float w1 = Wout[HH + h];

    float mem = 0.f, r = 0.f, s = 0.f;
    float bprev = 0.f;       // lanes 0..15: cluster-wide B_t; B_0 = 0
    float nz = g_pre[h];     // t = 0

    const unsigned mbar_local = smem_u32(&mbar);

    for (int t = 0; t < TT; t++) {
        // ============ consume: q_t = A_{t-1} + B_{t-1} (local smem) ========
        float q = 0.f;
        if (t > 0) {
            mbar_wait_parity(mbar_local, (t - 1) & 1u);
            const float* m = &msg[(t - 1) & 1][0][lane];
            float s0 = 0.f, s1 = 0.f, s2 = 0.f, s3 = 0.f;
#pragma unroll
            for (int c = 0; c < NCTA; c += 4) {
                s0 += m[(c + 0) * 32];
                s1 += m[(c + 1) * 32];
                s2 += m[(c + 2) * 32];
                s3 += m[(c + 3) * 32];
            }
            float sum  = (s0 + s1) + (s2 + s3);        // 0-15: ΣA, 16-31: ΣB_next
            float bnew = __shfl_down_sync(0xffffffffu, sum, 16);
            q = sum + bprev;                           // valid in lanes 0..15
            bprev = bnew;
        }

        // ============ I and membrane update ================================
        float i0 = nz, i1 = 0.f, i2 = 0.f, i3 = 0.f;
#pragma unroll
        for (int p = 0; p < PP; p += 4) {
            i0 += lp[p + 0] * __shfl_sync(0xffffffffu, q, p + 0);
            i1 += lp[p + 1] * __shfl_sync(0xffffffffu, q, p + 1);
            i2 += lp[p + 2] * __shfl_sync(0xffffffffu, q, p + 2);
            i3 += lp[p + 3] * __shfl_sync(0xffffffffu, q, p + 3);
        }
        const float I = (i0 + i1) + (i2 + i3);

        if (t + 1 < TT) nz = g_pre[(t + 1) * HH + h];   // prefetch next input

        const float reset = (mem > 0.5f) ? 0.5f : 0.0f; // from incoming mem
        mem = 0.9f * mem + I - reset;
        const bool spike = (mem > 0.5f);

        s = s * dr + (spike ? sg : 0.0f);
        r = dd * r + 0.005f * s;
        const float rbn = (dd * r + c005dr * s) * invcA; // rbar_{t+1}/(DT*sg)

        // ============ fold + publish [A_t | B_{t+1}] to all peers ==========
        float v[32];
#pragma unroll
        for (int p = 0; p < PP; p++) {
            v[p]      = spike ? kA[p] : 0.0f;  // A_t
            v[16 + p] = kA[p] * rbn;           // B_{t+1}
        }
        part[t & 1][warp][lane] = fold32(v, lane);
        __syncthreads();

        if (warp == 0) {
            const float* pb = &part[t & 1][0][lane];
            float a0 = 0.f, a1 = 0.f, a2 = 0.f, a3 = 0.f;
#pragma unroll
            for (int w = 0; w < NW; w += 4) {
                a0 += pb[(w + 0) * 32];
                a1 += pb[(w + 1) * 32];
                a2 += pb[(w + 2) * 32];
                a3 += pb[(w + 3) * 32];
            }
            const float acc = (a0 + a1) + (a2 + a3);

            // push my 128B message into every cluster CTA's smem
            const unsigned my_local = smem_u32(&msg[t & 1][rank][lane]);
#pragma unroll
            for (unsigned c = 0; c < NCTA; c++)
                st_cluster_f32(mapa_sh(my_local, c), acc);
            __syncwarp();   // order all lanes' stores before the arrives
            if (lane < NCTA)
                mbar_arrive_cluster(mapa_sh(mbar_local, (unsigned)lane));
        }

        // ============ y partials (off critical path) =======================
        float y0 = w0 * r, y1 = w1 * r;
#pragma unroll
        for (int o = 16; o > 0; o >>= 1) {
            y0 += __shfl_xor_sync(0xffffffffu, y0, o);
            y1 += __shfl_xor_sync(0xffffffffu, y1, o);
        }
        if (lane == 0) {
            float* gy = &g_y[((t * NCTA + (int)rank) * NW + warp) * 2];
            gy[0] = y0;
            gy[1] = y1;
        }
    }

    // No CTA may exit while peers' remote stores/arrives are in flight.
    cluster_sync();
}

// One warp per timestep sums the 128 per-warp partials (deterministic order).
__global__ void reduce_y(float* __restrict__ out)
{
    int t    = blockIdx.x * (blockDim.x / 32) + (threadIdx.x >> 5);
    int lane = threadIdx.x & 31;
    if (t < TT) {
        const float* base = &g_y[t * NCTA * NW * 2];
        float y0 = 0.f, y1 = 0.f;
#pragma unroll
        for (int j = 0; j < 4; j++) {
            int k = lane + j * 32;   // 0..127
            y0 += base[k * 2 + 0];
            y1 += base[k * 2 + 1];
        }
#pragma unroll
        for (int o = 16; o > 0; o >>= 1) {
            y0 += __shfl_xor_sync(0xffffffffu, y0, o);
            y1 += __shfl_xor_sync(0xffffffffu, y1, o);
        }
        if (lane == 0) {
            out[t * 2 + 0] = y0;
            out[t * 2 + 1] = y1;
        }
    }
}

extern "C" void kernel_launch(void* const* d_in, const int* in_sizes, int n_in,
                              void* d_out, int out_size)
{
    const float* x     = (const float*)d_in[0];
    const float* noise = (const float*)d_in[1];
    const float* Win   = (const float*)d_in[2];
    const float* Wout  = (const float*)d_in[3];
    const float* pin   = (const float*)d_in[4];
    const float* pout  = (const float*)d_in[5];
    const float* l     = (const float*)d_in[6];
    const float* stau  = (const float*)d_in[7];
    float* out = (float*)d_out;

    pre_kernel<<<(TT * HH + 255) / 256, 256>>>(noise, x, Win);
    snn_scan<<<NCTA, TPB>>>(Wout, pin, pout, l, stau);
    reduce_y<<<(TT + 7) / 8, 256>>>(out);
}

// round 6
// speedup vs baseline: 1.8727x; 1.1311x over previous
#include <cuda_runtime.h>

#define TT   1000
#define HH   4096
#define PP   16
#define NCTA 8           // one cluster of 8 CTAs
#define TPB  256         // 8 warps; 2 neurons per thread: 8*256*2 = 4096
#define NW   (TPB / 32)

// Scratch (device globals; no allocation). Rewritten identically every replay.
__device__ float g_y[TT * NCTA * NW * 2];    // per-warp y partials

// ---- PTX helpers (all proven in R5) ----------------------------------------
__device__ __forceinline__ unsigned smem_u32(const void* p) {
    return (unsigned)__cvta_generic_to_shared(p);
}
__device__ __forceinline__ unsigned mapa_sh(unsigned local, unsigned rank) {
    unsigned r;
    asm volatile("mapa.shared::cluster.u32 %0, %1, %2;" : "=r"(r) : "r"(local), "r"(rank));
    return r;
}
__device__ __forceinline__ void st_cluster_f32(unsigned addr, float v) {
    asm volatile("st.shared::cluster.f32 [%0], %1;" :: "r"(addr), "f"(v) : "memory");
}
__device__ __forceinline__ void mbar_init(unsigned addr, unsigned cnt) {
    asm volatile("mbarrier.init.shared.b64 [%0], %1;" :: "r"(addr), "r"(cnt) : "memory");
}
__device__ __forceinline__ void mbar_arrive_cluster(unsigned addr) {
    asm volatile("mbarrier.arrive.release.cluster.shared::cluster.b64 _, [%0];"
                 :: "r"(addr) : "memory");
}
__device__ __forceinline__ void mbar_wait_parity(unsigned addr, unsigned parity) {
    unsigned done;
    asm volatile(
        "{\n\t.reg .pred p;\n\t"
        "mbarrier.try_wait.parity.acquire.cluster.shared::cta.b64 p, [%1], %2;\n\t"
        "selp.b32 %0, 1, 0, p;\n\t}"
        : "=r"(done) : "r"(addr), "r"(parity) : "memory");
    if (!done) {
        asm volatile(
            "{\n\t.reg .pred P1;\n\t"
            "WL_%=:\n\t"
            "mbarrier.try_wait.parity.acquire.cluster.shared::cta.b64 P1, [%0], %1, 0x989680;\n\t"
            "@P1 bra.uni WD_%=;\n\t"
            "bra.uni WL_%=;\n\t"
            "WD_%=:\n\t}"
            :: "r"(addr), "r"(parity) : "memory");
    }
}
__device__ __forceinline__ void cluster_sync() {
    asm volatile("barrier.cluster.arrive.aligned;" ::: "memory");
    asm volatile("barrier.cluster.wait.aligned;" ::: "memory");
}
__device__ __forceinline__ unsigned ctarank() {
    unsigned r; asm("mov.u32 %0, %%cluster_ctarank;" : "=r"(r)); return r;
}
#define BAR_ARRIVE(id, n) asm volatile("bar.arrive %0, %1;" :: "r"(id), "r"(n) : "memory")
#define BAR_SYNC(id, n)   asm volatile("bar.sync %0, %1;"   :: "r"(id), "r"(n) : "memory")

// Warp-wide reduction of 32 per-lane values in 31 shuffles (5 dependent
// levels). On return, value j (summed over all lanes) is held by lane j.
__device__ __forceinline__ float fold32(float v[32], int lane) {
#pragma unroll
    for (int m = 16; m >= 1; m >>= 1) {
        const bool hi = (lane & m) != 0;
#pragma unroll
        for (int i = 0; i < m; i++) {
            float keep = hi ? v[i + m] : v[i];
            float send = hi ? v[i] : v[i + m];
            float recv = __shfl_xor_sync(0xffffffffu, send, m);
            v[i] = keep + recv;
        }
    }
    return v[0];
}

__global__ void __launch_bounds__(TPB, 1) __cluster_dims__(NCTA, 1, 1)
snn_scan(const float* __restrict__ x,      // [T,6]
         const float* __restrict__ noise,  // [T,H]
         const float* __restrict__ Win,    // [H,6]
         const float* __restrict__ Wout,   // [2,H]
         const float* __restrict__ pin,    // [H,16]
         const float* __restrict__ pout,   // [H,16]
         const float* __restrict__ l,      // [16]
         const float* __restrict__ stau)   // [H]
{
    const int tid  = threadIdx.x;
    const int lane = tid & 31;
    const int warp = tid >> 5;
    const unsigned rank = ctarank();
    const int hA = (int)rank * TPB + tid;      // neuron A: 0..2047
    const int hB = hA + 2048;                  // neuron B: 2048..4095

    // msg[slot][producer][32] = [A_t(0..15) | B_{t+1}(16..31)]
    __shared__ __align__(128) float msg[2][NCTA][32];
    __shared__ __align__(128) float part[2][NW][32];
    __shared__ __align__(16)  unsigned long long mbars[NCTA];  // one per producer

    if (tid < NCTA) mbar_init(smem_u32(&mbars[tid]), 1);
    __syncthreads();
    cluster_sync();   // all barriers initialized before any remote arrive

    // ---- per-neuron constants (x2) in registers ----
    const float dr     = 0.08208499862389880f;   // exp(-DT/TAU_R)
    const float c005dr = 0.005f * dr;

    const float tauA = 1.0f / (1.0f + expf(-stau[hA])) * 0.03f + 0.02f;
    const float tauB = 1.0f / (1.0f + expf(-stau[hB])) * 0.03f + 0.02f;
    const float ddA  = expf(-0.005f / tauA), ddB = expf(-0.005f / tauB);
    const float sgA  = 2.5f / tauA,          sgB = 2.5f / tauB;   // DT/(tau*TAU_R)
    const float icA  = tauA * 80.0f,         icB = tauB * 80.0f;  // 1/(DT*sg)

    float lpA[PP], lpB[PP], kAA[PP], kAB[PP];
#pragma unroll
    for (int p = 0; p < PP; p++) {
        lpA[p] = l[p] * pin[hA * PP + p];
        lpB[p] = l[p] * pin[hB * PP + p];
        kAA[p] = pout[hA * PP + p] * (0.0125f / tauA);   // po * DT * sg
        kAB[p] = pout[hB * PP + p] * (0.0125f / tauB);
    }
    float wvA[6], wvB[6];
#pragma unroll
    for (int k = 0; k < 6; k++) { wvA[k] = Win[hA * 6 + k]; wvB[k] = Win[hB * 6 + k]; }
    const float w0A = Wout[hA], w1A = Wout[HH + hA];
    const float w0B = Wout[hB], w1B = Wout[HH + hB];

    float memA = 0.f, rA = 0.f, sA = 0.f;
    float memB = 0.f, rB = 0.f, sB = 0.f;
    float bprev = 0.f;          // lanes 0..15: cluster-wide B_t; B_0 = 0

    // input terms for step t (computed in previous step's slack)
    float preA, preB;
    {
        float xa = x[0], xb = x[1], xc = x[2], xd = x[3], xe = x[4], xf = x[5];
        preA = noise[hA] * 0.1f + wvA[0]*xa + wvA[1]*xb + wvA[2]*xc + wvA[3]*xd + wvA[4]*xe + wvA[5]*xf;
        preB = noise[hB] * 0.1f + wvB[0]*xa + wvB[1]*xb + wvB[2]*xc + wvB[3]*xd + wvB[4]*xe + wvB[5]*xf;
    }

    const unsigned mb_local = smem_u32(&mbars[0]);

    for (int t = 0; t < TT; t++) {
        // ============ consume: q_t = A_{t-1} + B_{t-1} (local smem) ========
        float q = 0.f;
        if (t > 0) {
            if (lane < NCTA)
                mbar_wait_parity(mb_local + (unsigned)lane * 8u, (t - 1) & 1u);
            __syncwarp();
            const float* m = &msg[(t - 1) & 1][0][lane];
            float s0 = (m[0 * 32] + m[1 * 32]) + (m[2 * 32] + m[3 * 32]);
            float s1 = (m[4 * 32] + m[5 * 32]) + (m[6 * 32] + m[7 * 32]);
            float sum  = s0 + s1;                       // 0-15: ΣA, 16-31: ΣB_next
            float bnew = __shfl_down_sync(0xffffffffu, sum, 16);
            q = sum + bprev;                            // valid in lanes 0..15
            bprev = bnew;
        }

        // ============ I and membrane update (2 neurons) ====================
        float iA0 = preA, iA1 = 0.f, iB0 = preB, iB1 = 0.f;
#pragma unroll
        for (int p = 0; p < PP; p += 2) {
            float q0 = __shfl_sync(0xffffffffu, q, p + 0);
            float q1 = __shfl_sync(0xffffffffu, q, p + 1);
            iA0 += lpA[p + 0] * q0;  iA1 += lpA[p + 1] * q1;
            iB0 += lpB[p + 0] * q0;  iB1 += lpB[p + 1] * q1;
        }
        const float IA = iA0 + iA1, IB = iB0 + iB1;

        memA = 0.9f * memA + IA - ((memA > 0.5f) ? 0.5f : 0.0f);
        memB = 0.9f * memB + IB - ((memB > 0.5f) ? 0.5f : 0.0f);
        const bool spkA = (memA > 0.5f), spkB = (memB > 0.5f);

        sA = sA * dr + (spkA ? sgA : 0.0f);
        sB = sB * dr + (spkB ? sgB : 0.0f);
        rA = ddA * rA + 0.005f * sA;
        rB = ddB * rB + 0.005f * sB;
        const float rbnA = (ddA * rA + c005dr * sA) * icA;  // rbar_{t+1}/(DT*sg)
        const float rbnB = (ddB * rB + c005dr * sB) * icB;

        // ============ fold + hand off partial ==============================
        float v[32];
#pragma unroll
        for (int p = 0; p < PP; p++) {
            v[p]      = (spkA ? kAA[p] : 0.0f) + (spkB ? kAB[p] : 0.0f);  // A_t
            v[16 + p] = kAA[p] * rbnA + kAB[p] * rbnB;                    // B_{t+1}
        }
        part[t & 1][warp][lane] = fold32(v, lane);

        if (warp != 0) {
            BAR_ARRIVE(1, TPB);        // hand off, do not stall
        } else {
            BAR_SYNC(1, TPB);          // wait for all partials (drains STS)
            const float* pb = &part[t & 1][0][lane];
            float a0 = (pb[0 * 32] + pb[1 * 32]) + (pb[2 * 32] + pb[3 * 32]);
            float a1 = (pb[4 * 32] + pb[5 * 32]) + (pb[6 * 32] + pb[7 * 32]);
            const float acc = a0 + a1;

            // push my 128B message into every cluster CTA's smem
            const unsigned my_local = smem_u32(&msg[t & 1][rank][lane]);
#pragma unroll
            for (unsigned c = 0; c < NCTA; c++)
                st_cluster_f32(mapa_sh(my_local, c), acc);
            __syncwarp();              // all lanes' stores before the arrives
            if (lane < NCTA)           // arrive at slot <rank> of CTA <lane>
                mbar_arrive_cluster(mapa_sh(mb_local + rank * 8u, (unsigned)lane));
        }

        // ============ slack work (off the forward chain) ===================
        float y0 = w0A * rA + w0B * rB;
        float y1 = w1A * rA + w1B * rB;
#pragma unroll
        for (int o = 16; o > 0; o >>= 1) {
            y0 += __shfl_xor_sync(0xffffffffu, y0, o);
            y1 += __shfl_xor_sync(0xffffffffu, y1, o);
        }
        if (lane == 0) {
            float* gy = &g_y[((t * NCTA + (int)rank) * NW + warp) * 2];
            gy[0] = y0;
            gy[1] = y1;
        }

        // prefetch + precompute next step's input terms
        if (t + 1 < TT) {
            const float* xr = &x[(t + 1) * 6];
            float xa = xr[0], xb = xr[1], xc = xr[2], xd = xr[3], xe = xr[4], xf = xr[5];
            preA = noise[(t + 1) * HH + hA] * 0.1f
                 + wvA[0]*xa + wvA[1]*xb + wvA[2]*xc + wvA[3]*xd + wvA[4]*xe + wvA[5]*xf;
            preB = noise[(t + 1) * HH + hB] * 0.1f
                 + wvB[0]*xa + wvB[1]*xb + wvB[2]*xc + wvB[3]*xd + wvB[4]*xe + wvB[5]*xf;
        }
    }

    // No CTA may exit while peers' remote stores/arrives are in flight.
    cluster_sync();
}

// One warp per timestep sums the 64 per-warp partials (deterministic order).
__global__ void reduce_y(float* __restrict__ out)
{
    int t    = blockIdx.x * (blockDim.x / 32) + (threadIdx.x >> 5);
    int lane = threadIdx.x & 31;
    if (t < TT) {
        const float* base = &g_y[t * NCTA * NW * 2];
        float y0 = 0.f, y1 = 0.f;
#pragma unroll
        for (int j = 0; j < 2; j++) {
            int k = lane + j * 32;    // 0..63
            y0 += base[k * 2 + 0];
            y1 += base[k * 2 + 1];
        }
#pragma unroll
        for (int o = 16; o > 0; o >>= 1) {
            y0 += __shfl_xor_sync(0xffffffffu, y0, o);
            y1 += __shfl_xor_sync(0xffffffffu, y1, o);
        }
        if (lane == 0) {
            out[t * 2 + 0] = y0;
            out[t * 2 + 1] = y1;
        }
    }
}

extern "C" void kernel_launch(void* const* d_in, const int* in_sizes, int n_in,
                              void* d_out, int out_size)
{
    const float* x     = (const float*)d_in[0];
    const float* noise = (const float*)d_in[1];
    const float* Win   = (const float*)d_in[2];
    const float* Wout  = (const float*)d_in[3];
    const float* pin   = (const float*)d_in[4];
    const float* pout  = (const float*)d_in[5];
    const float* l     = (const float*)d_in[6];
    const float* stau  = (const float*)d_in[7];
    float* out = (float*)d_out;

    snn_scan<<<NCTA, TPB>>>(x, noise, Win, Wout, pin, pout, l, stau);
    reduce_y<<<(TT + 7) / 8, 256>>>(out);
}

// round 7
// speedup vs baseline: 2.3273x; 1.2428x over previous
#include <cuda_runtime.h>

#define TT   1000
#define HH   4096
#define PP   16
#define NCTA 8           // one cluster of 8 CTAs
#define TPB  128         // 4 warps; 4 neurons/thread: 8*128*4 = 4096
#define NW   (TPB / 32)
#define NN   4           // neurons per thread

// Scratch (device globals; no allocation). Rewritten identically every replay.
__device__ float g_pre[TT * HH];   // Win@x + noise/10
__device__ float g_r[TT * HH];     // r_t[h] trace (consumed by y_kernel)

// ---- PTX helpers ------------------------------------------------------------
__device__ __forceinline__ unsigned smem_u32(const void* p) {
    return (unsigned)__cvta_generic_to_shared(p);
}
__device__ __forceinline__ unsigned mapa_sh(unsigned local, unsigned rank) {
    unsigned r;
    asm volatile("mapa.shared::cluster.u32 %0, %1, %2;" : "=r"(r) : "r"(local), "r"(rank));
    return r;
}
__device__ __forceinline__ void st_cluster_f32(unsigned addr, float v) {
    asm volatile("st.shared::cluster.f32 [%0], %1;" :: "r"(addr), "f"(v) : "memory");
}
__device__ __forceinline__ void st_rel_cluster_u32(unsigned addr, unsigned v) {
    asm volatile("st.release.cluster.shared::cluster.u32 [%0], %1;"
                 :: "r"(addr), "r"(v) : "memory");
}
__device__ __forceinline__ unsigned ld_acq_cluster(unsigned addr) {
    unsigned v;
    asm volatile("ld.acquire.cluster.shared::cta.u32 %0, [%1];"
                 : "=r"(v) : "r"(addr) : "memory");
    return v;
}
__device__ __forceinline__ void cluster_sync() {
    asm volatile("barrier.cluster.arrive.aligned;" ::: "memory");
    asm volatile("barrier.cluster.wait.aligned;" ::: "memory");
}
__device__ __forceinline__ unsigned ctarank() {
    unsigned r; asm("mov.u32 %0, %%cluster_ctarank;" : "=r"(r)); return r;
}
#define BAR_ARRIVE(id, n) asm volatile("bar.arrive %0, %1;" :: "r"(id), "r"(n) : "memory")
#define BAR_SYNC(id, n)   asm volatile("bar.sync %0, %1;"   :: "r"(id), "r"(n) : "memory")

// Warp-wide reduction of 32 per-lane values in 31 shuffles (5 dependent
// levels). On return, value j (summed over all lanes) is held by lane j.
__device__ __forceinline__ float fold32(float v[32], int lane) {
#pragma unroll
    for (int m = 16; m >= 1; m >>= 1) {
        const bool hi = (lane & m) != 0;
#pragma unroll
        for (int i = 0; i < m; i++) {
            float keep = hi ? v[i + m] : v[i];
            float send = hi ? v[i] : v[i + m];
            float recv = __shfl_xor_sync(0xffffffffu, send, m);
            v[i] = keep + recv;
        }
    }
    return v[0];
}

// pre[t][h] = Win[h,:]@x[t,:] + noise[t,h]/10
__global__ void pre_kernel(const float* __restrict__ noise,
                           const float* __restrict__ x,
                           const float* __restrict__ Win)
{
    int i = blockIdx.x * blockDim.x + threadIdx.x;
    if (i < TT * HH) {
        int t = i / HH, h = i - t * HH;
        float acc = noise[i] * 0.1f;
        const float* wr = &Win[h * 6];
        const float* xr = &x[t * 6];
#pragma unroll
        for (int k = 0; k < 6; k++) acc += wr[k] * xr[k];
        g_pre[i] = acc;
    }
}

__global__ void __launch_bounds__(TPB, 1) __cluster_dims__(NCTA, 1, 1)
snn_scan(const float* __restrict__ pin,    // [H,16]
         const float* __restrict__ pout,   // [H,16]
         const float* __restrict__ l,      // [16]
         const float* __restrict__ stau)   // [H]
{
    const int tid  = threadIdx.x;
    const int lane = tid & 31;
    const int warp = tid >> 5;
    const unsigned rank = ctarank();

    // msg[slot][producer][32] = [A_t(0..15) | B_{t+1}(16..31)]
    __shared__ __align__(128) float    msg[2][NCTA][32];
    __shared__ __align__(128) float    part[2][NW][32];
    __shared__ __align__(64)  unsigned flg[2][NCTA];   // monotonic tags

    if (tid < 2 * NCTA) ((unsigned*)flg)[tid] = 0u;
    __syncthreads();
    cluster_sync();   // zero-init visible before any remote store

    // ---- per-neuron constants (x4) in registers ----
    const float drc    = 0.08208499862389880f;   // exp(-DT/TAU_R)
    const float c005dr = 0.005f * drc;

    int hh[NN];
    float dd[NN], sg[NN], ic[NN];
    float lp[NN][PP], kA[NN][PP];
#pragma unroll
    for (int k = 0; k < NN; k++) {
        hh[k] = (int)rank * TPB + tid + k * (NCTA * TPB);
        const float tau = 1.0f / (1.0f + expf(-stau[hh[k]])) * 0.03f + 0.02f;
        dd[k] = expf(-0.005f / tau);
        sg[k] = 2.5f / tau;                 // DT/(tau*TAU_R)
        ic[k] = tau * 80.0f;                // 1/(DT*sg)
#pragma unroll
        for (int p = 0; p < PP; p++) {
            lp[k][p] = l[p] * pin[hh[k] * PP + p];
            kA[k][p] = pout[hh[k] * PP + p] * (0.0125f / tau);   // po*DT*sg
        }
    }

    float mem[NN], rr[NN], ss[NN], pre[NN];
#pragma unroll
    for (int k = 0; k < NN; k++) {
        mem[k] = 0.f; rr[k] = 0.f; ss[k] = 0.f;
        pre[k] = g_pre[hh[k]];    // t = 0
    }
    float bprev = 0.f;            // lanes 0..15: cluster-wide B_t; B_0 = 0

    const unsigned flg_base = smem_u32(&flg[0][0]);
    const unsigned msg_base = smem_u32(&msg[0][0][0]);

    for (int t = 0; t < TT; t++) {
        // ============ consume: q_t = A_{t-1} + B_{t-1} (local smem) ========
        float q = 0.f;
        if (t > 0) {
            const int sl = (t - 1) & 1;
            if (lane < NCTA) {
                const unsigned fa = flg_base + (unsigned)(sl * NCTA + lane) * 4u;
                while (ld_acq_cluster(fa) != (unsigned)t) {}
            }
            __syncwarp();
            const float* m = &msg[sl][0][lane];
            float s0 = (m[0 * 32] + m[1 * 32]) + (m[2 * 32] + m[3 * 32]);
            float s1 = (m[4 * 32] + m[5 * 32]) + (m[6 * 32] + m[7 * 32]);
            float sum  = s0 + s1;                      // 0-15: ΣA, 16-31: ΣB_next
            float bnew = __shfl_down_sync(0xffffffffu, sum, 16);
            q = sum + bprev;                           // valid in lanes 0..15
            bprev = bnew;
        }

        // ============ I and membrane update (4 neurons) ====================
        float acc[NN];
#pragma unroll
        for (int k = 0; k < NN; k++) acc[k] = pre[k];
#pragma unroll
        for (int p = 0; p < PP; p++) {
            const float qp = __shfl_sync(0xffffffffu, q, p);
#pragma unroll
            for (int k = 0; k < NN; k++) acc[k] += lp[k][p] * qp;
        }

        float f[NN], rbn[NN];
#pragma unroll
        for (int k = 0; k < NN; k++) {
            mem[k] = 0.9f * mem[k] + acc[k] - ((mem[k] > 0.5f) ? 0.5f : 0.0f);
            f[k]   = (mem[k] > 0.5f) ? 1.0f : 0.0f;
            ss[k]  = ss[k] * drc + f[k] * sg[k];
            rr[k]  = dd[k] * rr[k] + 0.005f * ss[k];
            rbn[k] = (dd[k] * rr[k] + c005dr * ss[k]) * ic[k];  // rbar_{t+1}/(DT*sg)
        }

        // ============ fold + hand off partial ==============================
        float v[32];
#pragma unroll
        for (int p = 0; p < PP; p++) {
            v[p]      = (f[0] * kA[0][p] + f[1] * kA[1][p])
                      + (f[2] * kA[2][p] + f[3] * kA[3][p]);        // A_t
            v[16 + p] = (rbn[0] * kA[0][p] + rbn[1] * kA[1][p])
                      + (rbn[2] * kA[2][p] + rbn[3] * kA[3][p]);    // B_{t+1}
        }
        part[t & 1][warp][lane] = fold32(v, lane);

        if (warp != 0) {
            BAR_ARRIVE(1, TPB);       // hand off, don't stall
        } else {
            BAR_SYNC(1, TPB);         // wait for all partials (drains STS)
            const float* pb = &part[t & 1][0][lane];
            const float accm = (pb[0 * 32] + pb[1 * 32]) + (pb[2 * 32] + pb[3 * 32]);

            // push my 128B message into every cluster CTA's smem
            const unsigned my_msg = msg_base
                + (unsigned)(((t & 1) * NCTA + (int)rank) * 32 + lane) * 4u;
#pragma unroll
            for (unsigned c = 0; c < NCTA; c++)
                st_cluster_f32(mapa_sh(my_msg, c), accm);
            __syncwarp();             // all lanes' data stores before the flags
            if (lane < NCTA) {
                const unsigned my_flg = flg_base
                    + (unsigned)((t & 1) * NCTA + (int)rank) * 4u;
                st_rel_cluster_u32(mapa_sh(my_flg, (unsigned)lane), (unsigned)(t + 1));
            }
        }

        // ============ slack: store r trace + prefetch next input ==========
        const int tn = (t + 1 < TT) ? (t + 1) : t;
#pragma unroll
        for (int k = 0; k < NN; k++) {
            g_r[t * HH + hh[k]] = rr[k];
            pre[k] = g_pre[tn * HH + hh[k]];
        }
    }

    // No CTA may exit while peers' remote stores are in flight.
    cluster_sync();
}

// y[t,o] = Wout[o,:] @ r[t,:]  — one block per timestep, deterministic order.
__global__ void __launch_bounds__(256) y_kernel(const float* __restrict__ Wout,
                                                float* __restrict__ out)
{
    const int t   = blockIdx.x;
    const int tid = threadIdx.x;
    const int lane = tid & 31, warp = tid >> 5;
    float y0 = 0.f, y1 = 0.f;
#pragma unroll
    for (int j = 0; j < HH / 256; j++) {
        const int h  = tid + j * 256;
        const float rv = g_r[t * HH + h];
        y0 += Wout[h] * rv;
        y1 += Wout[HH + h] * rv;
    }
#pragma unroll
    for (int o = 16; o > 0; o >>= 1) {
        y0 += __shfl_xor_sync(0xffffffffu, y0, o);
        y1 += __shfl_xor_sync(0xffffffffu, y1, o);
    }
    __shared__ float s0[8], s1[8];
    if (lane == 0) { s0[warp] = y0; s1[warp] = y1; }
    __syncthreads();
    if (tid == 0) {
        float a0 = 0.f, a1 = 0.f;
#pragma unroll
        for (int w = 0; w < 8; w++) { a0 += s0[w]; a1 += s1[w]; }
        out[t * 2 + 0] = a0;
        out[t * 2 + 1] = a1;
    }
}

extern "C" void kernel_launch(void* const* d_in, const int* in_sizes, int n_in,
                              void* d_out, int out_size)
{
    const float* x     = (const float*)d_in[0];
    const float* noise = (const float*)d_in[1];
    const float* Win   = (const float*)d_in[2];
    const float* Wout  = (const float*)d_in[3];
    const float* pin   = (const float*)d_in[4];
    const float* pout  = (const float*)d_in[5];
    const float* l     = (const float*)d_in[6];
    const float* stau  = (const float*)d_in[7];
    float* out = (float*)d_out;

    pre_kernel<<<(TT * HH + 255) / 256, 256>>>(noise, x, Win);
    snn_scan<<<NCTA, TPB>>>(pin, pout, l, stau);
    y_kernel<<<TT, 256>>>(Wout, out);
}